// round 12
// baseline (speedup 1.0000x reference)
#include <cuda_runtime.h>
#include <cuda_fp16.h>
#include <cstdint>

constexpr int C_DIM  = 512;
constexpr int NHEADS = 8;
constexpr int HD     = 64;
constexpr int NB     = 8;
constexpr int NSEQ   = 1024;
constexpr int M_TOT  = NB * NSEQ;     // 8192
constexpr int KVN    = 2 * C_DIM;     // 1024
constexpr float SCALE = 0.125f;

// fp16 planes: kv result, converted inputs
__device__ __half g_kvh[2][(size_t)M_TOT * KVN];
__device__ __half g_xh[2][(size_t)M_TOT * C_DIM];
__device__ __half g_wh[2][(size_t)C_DIM * KVN];

// ---------------------------------------------------------------------------
__device__ __forceinline__ uint32_t smem_u32(const void* p) {
    return (uint32_t)__cvta_generic_to_shared(p);
}
__device__ __forceinline__ void ldsm_x4(uint32_t* r, uint32_t a) {
    asm volatile("ldmatrix.sync.aligned.m8n8.x4.shared.b16 {%0,%1,%2,%3}, [%4];"
                 : "=r"(r[0]), "=r"(r[1]), "=r"(r[2]), "=r"(r[3]) : "r"(a));
}
__device__ __forceinline__ void ldsm_x4t(uint32_t* r, uint32_t a) {
    asm volatile("ldmatrix.sync.aligned.m8n8.x4.trans.shared.b16 {%0,%1,%2,%3}, [%4];"
                 : "=r"(r[0]), "=r"(r[1]), "=r"(r[2]), "=r"(r[3]) : "r"(a));
}
__device__ __forceinline__ void mmaH(float* c, const uint32_t* a, const uint32_t* b) {
    asm volatile("mma.sync.aligned.m16n8k16.row.col.f32.f16.f16.f32 "
                 "{%0,%1,%2,%3}, {%4,%5,%6,%7}, {%8,%9}, {%0,%1,%2,%3};"
                 : "+f"(c[0]), "+f"(c[1]), "+f"(c[2]), "+f"(c[3])
                 : "r"(a[0]), "r"(a[1]), "r"(a[2]), "r"(a[3]), "r"(b[0]), "r"(b[1]));
}
__device__ __forceinline__ uint32_t packH(float x0, float x1) {
    __half2 h = __floats2half2_rn(x0, x1);
    return *reinterpret_cast<uint32_t*>(&h);
}
__device__ __forceinline__ void cp16(uint32_t s, const void* g) {
    asm volatile("cp.async.cg.shared.global [%0], [%1], 16;" :: "r"(s), "l"(g));
}
__device__ __forceinline__ void cp_commit() { asm volatile("cp.async.commit_group;"); }
__device__ __forceinline__ void cp_wait0()  { asm volatile("cp.async.wait_group 0;"); }

// ---------------------------------------------------------------------------
// Kernel 0: convert x1/x2/w1/w2 -> fp16 planes.
// ---------------------------------------------------------------------------
constexpr int XN4 = M_TOT * C_DIM / 4;
constexpr int WN4 = C_DIM * KVN / 4;
constexpr int TOT4 = 2 * XN4 + 2 * WN4;

__global__ __launch_bounds__(256) void split_all(const float* __restrict__ x1,
                                                 const float* __restrict__ x2,
                                                 const float* __restrict__ w1,
                                                 const float* __restrict__ w2,
                                                 __half* __restrict__ xh,
                                                 __half* __restrict__ wh) {
    const int i = blockIdx.x * blockDim.x + threadIdx.x;
    if (i >= TOT4) return;
    const float* s;
    __half* d;
    size_t off;
    if (i < XN4)                { s = x1; d = xh;                                off = i; }
    else if (i < 2 * XN4)       { s = x2; d = xh + (size_t)M_TOT * C_DIM;        off = i - XN4; }
    else if (i < 2 * XN4 + WN4) { s = w1; d = wh;                                off = i - 2 * XN4; }
    else                        { s = w2; d = wh + (size_t)C_DIM * KVN;          off = i - 2 * XN4 - WN4; }
    const float4 v = *(const float4*)&s[off * 4];
    uint2 hv = {packH(v.x, v.y), packH(v.z, v.w)};
    *(uint2*)&d[off * 4] = hv;
}

// ---------------------------------------------------------------------------
// Kernel 1: kv = x @ W, pure fp16 (unchanged from round 11).
// ---------------------------------------------------------------------------
constexpr int XPAD = 40;
constexpr int WPAD = 136;
constexpr int XT = 128 * XPAD;
constexpr int WT = 32 * WPAD;
constexpr int KV_SMEM = (2 * XT + 2 * WT) * 2;   // 37888 B

__global__ __launch_bounds__(256, 1) void kv_gemm(int dummy) {
    extern __shared__ __half ksm[];
    const int br = blockIdx.z;
    const __half* __restrict__ XH_g = g_xh[br];
    const __half* __restrict__ WH_g = g_wh[br];
    __half* __restrict__ Oh = g_kvh[br];

    const int t    = threadIdx.x;
    const int w    = t >> 5;
    const int lane = t & 31;
    const int g    = lane >> 2;
    const int tq   = lane & 3;
    const int wm   = w >> 2;
    const int wn   = w & 3;
    const int m0   = blockIdx.y * 128;
    const int n0   = blockIdx.x * 128;

    const int a_row = wm * 64 + (lane & 7) + ((lane >> 3) & 1) * 8;
    const int a_col = ((lane >> 4) & 1) * 8;
    const int b_quad = lane >> 3;
    const int b_r    = lane & 7;

    const int xr0 = (t + 0)   >> 2, xc0 = ((t + 0)   & 3) * 8;
    const int xr1 = (t + 256) >> 2, xc1 = ((t + 256) & 3) * 8;
    const int wr0 = (t + 0)   >> 4, wc0 = ((t + 0)   & 15) * 8;
    const int wr1 = (t + 256) >> 4, wc1 = ((t + 256) & 15) * 8;

    auto issue = [&](int k0, int p) {
        __half* XH = ksm + p * XT;
        __half* WH = ksm + 2 * XT + p * WT;
        cp16(smem_u32(&XH[xr0 * XPAD + xc0]), &XH_g[(size_t)(m0 + xr0) * C_DIM + k0 + xc0]);
        cp16(smem_u32(&XH[xr1 * XPAD + xc1]), &XH_g[(size_t)(m0 + xr1) * C_DIM + k0 + xc1]);
        cp16(smem_u32(&WH[wr0 * WPAD + wc0]), &WH_g[(size_t)(k0 + wr0) * KVN + n0 + wc0]);
        cp16(smem_u32(&WH[wr1 * WPAD + wc1]), &WH_g[(size_t)(k0 + wr1) * KVN + n0 + wc1]);
        cp_commit();
    };

    float acc[4][4][4] = {};

    issue(0, 0);
    for (int ki = 0; ki < 16; ki++) {
        cp_wait0();
        __syncthreads();
        if (ki + 1 < 16) issue((ki + 1) * 32, (ki + 1) & 1);
        const int p = ki & 1;
        const __half* XH = ksm + p * XT;
        const __half* WH = ksm + 2 * XT + p * WT;

        #pragma unroll
        for (int ks = 0; ks < 2; ks++) {
            uint32_t ah[4][4];
            #pragma unroll
            for (int mi = 0; mi < 4; mi++) {
                const int addr = (a_row + mi * 16) * XPAD + ks * 16 + a_col;
                ldsm_x4(ah[mi], smem_u32(&XH[addr]));
            }
            uint32_t bh[2][4];
            #pragma unroll
            for (int nip = 0; nip < 2; nip++) {
                const int row = ks * 16 + (b_quad & 1) * 8 + b_r;
                const int col = wn * 32 + nip * 16 + (b_quad >> 1) * 8;
                ldsm_x4t(bh[nip], smem_u32(&WH[row * WPAD + col]));
            }
            #pragma unroll
            for (int mi = 0; mi < 4; mi++)
                #pragma unroll
                for (int nn = 0; nn < 4; nn++)
                    mmaH(acc[mi][nn], ah[mi], &bh[nn >> 1][(nn & 1) * 2]);
        }
        __syncthreads();
    }

    #pragma unroll
    for (int mi = 0; mi < 4; mi++)
        #pragma unroll
        for (int nn = 0; nn < 4; nn++) {
            const int row = m0 + wm * 64 + mi * 16 + g;
            const int col = n0 + wn * 32 + nn * 8 + 2 * tq;
            *(uint32_t*)&Oh[(size_t)row * KVN + col] = packH(acc[mi][nn][0], acc[mi][nn][1]);
            *(uint32_t*)&Oh[(size_t)(row + 8) * KVN + col] = packH(acc[mi][nn][2], acc[mi][nn][3]);
        }
}

// ---------------------------------------------------------------------------
// Kernel 2: fused cross attention, 32 q-rows per warp (K/V frags reused x2).
// CTA = 256 q rows; 8 warps; warp w owns rows [32w, 32w+32).
// smem: QH 256x88 + 2 x (KH, VH 128x88) = 135168 B, 1 CTA/SM.
// ---------------------------------------------------------------------------
constexpr int PAD = 88;
constexpr int KV_ELE = 128 * PAD;     // 11264
constexpr int Q_ELE  = 256 * PAD;     // 22528
constexpr int ATTN_SMEM = (Q_ELE + 4 * KV_ELE) * 2;   // 135168 B

__global__ __launch_bounds__(256, 1) void attn_kernel(const float* __restrict__ x1,
                                                      const float* __restrict__ x2,
                                                      float* __restrict__ out) {
    extern __shared__ __half smb[];
    __half* QH = smb;

    const int br = blockIdx.z;
    const int bh = blockIdx.y;
    const int bb = bh >> 3;
    const int hh = bh & 7;
    const int qt = blockIdx.x;

    const float* __restrict__ q_g = (br ? x2 : x1)
        + (size_t)bb * NSEQ * C_DIM + (size_t)qt * 256 * C_DIM + hh * HD;
    const __half* __restrict__ KHg = g_kvh[1 - br];
    const __half* __restrict__ VHg = g_kvh[br];
    float* __restrict__ o_g = out + (size_t)br * NB * NSEQ * C_DIM
        + (size_t)bb * NSEQ * C_DIM + (size_t)qt * 256 * C_DIM + hh * HD;

    const int tid  = threadIdx.x;
    const int w    = tid >> 5;
    const int lane = tid & 31;
    const int g    = lane >> 2;
    const int tq   = lane & 3;

    const size_t kv_row0 = (size_t)bb * NSEQ;
    const int kcol = hh * HD;
    const int vcol = C_DIM + hh * HD;

    int cm[4], cd[4];
    #pragma unroll
    for (int l = 0; l < 4; l++) {
        const int c = tid + l * 256;
        cm[l] = c >> 3;
        cd[l] = (c & 7) * 8;
    }

    auto issue = [&](int mt, int p) {
        __half* KH = smb + Q_ELE + (p * 2 + 0) * KV_ELE;
        __half* VH = smb + Q_ELE + (p * 2 + 1) * KV_ELE;
        const size_t rbase = kv_row0 + (size_t)mt * 128;
        #pragma unroll
        for (int l = 0; l < 4; l++) {
            const size_t gidx = (rbase + cm[l]) * KVN;
            const int so = cm[l] * PAD + cd[l];
            cp16(smem_u32(&KH[so]), &KHg[gidx + kcol + cd[l]]);
            cp16(smem_u32(&VH[so]), &VHg[gidx + vcol + cd[l]]);
        }
        cp_commit();
    };

    // ---- prologue: issue tile 0; load + scale + round Q (256 x 64) ----
    issue(0, 0);
    #pragma unroll
    for (int l = 0; l < 16; l++) {
        const int c   = tid + l * 256;
        const int row = c >> 4;
        const int c4  = (c & 15) * 4;
        float4 q4 = *(const float4*)&q_g[(size_t)row * C_DIM + c4];
        uint2 hv = {packH(q4.x * SCALE, q4.y * SCALE), packH(q4.z * SCALE, q4.w * SCALE)};
        *(uint2*)&QH[row * PAD + c4] = hv;
    }
    __syncthreads();

    // loop-invariant Q fragments: 2 m-tiles per warp
    const int a_row_off = (lane & 7) + ((lane >> 3) & 1) * 8;
    const int a_col_off = ((lane >> 4) & 1) * 8;
    uint32_t ah[2][16];
    #pragma unroll
    for (int mi = 0; mi < 2; mi++)
        #pragma unroll
        for (int ks = 0; ks < 4; ks++) {
            const int arow = w * 32 + mi * 16 + a_row_off;
            const int acol = ks * 16 + a_col_off;
            ldsm_x4(&ah[mi][ks * 4], smem_u32(&QH[arow * PAD + acol]));
        }

    float oacc[2][8][4] = {};
    const int b_quad = lane >> 3;
    const int b_r    = lane & 7;

    for (int mt = 0; mt < 8; mt++) {
        cp_wait0();
        __syncthreads();
        if (mt + 1 < 8) issue(mt + 1, (mt + 1) & 1);

        const int p = mt & 1;
        const __half* KH = smb + Q_ELE + (p * 2 + 0) * KV_ELE;
        const __half* VH = smb + Q_ELE + (p * 2 + 1) * KV_ELE;

        #pragma unroll
        for (int j = 0; j < 8; j++) {
            const int bcol  = b_quad * 8;
            const int brow0 = (2 * j + 0) * 8 + b_r;
            const int brow1 = (2 * j + 1) * 8 + b_r;
            uint32_t bh0[8], bh1[8];
            ldsm_x4(&bh0[0], smem_u32(&KH[brow0 * PAD + bcol]));
            ldsm_x4(&bh0[4], smem_u32(&KH[brow0 * PAD + 32 + bcol]));
            ldsm_x4(&bh1[0], smem_u32(&KH[brow1 * PAD + bcol]));
            ldsm_x4(&bh1[4], smem_u32(&KH[brow1 * PAD + 32 + bcol]));

            // ---- stage 1 for both m-tiles (K frags reused) ----
            uint32_t sah[2][4];
            #pragma unroll
            for (int mi = 0; mi < 2; mi++) {
                float s0a[4] = {}, s0b[4] = {}, s1a[4] = {}, s1b[4] = {};
                #pragma unroll
                for (int ks = 0; ks < 2; ks++) {
                    mmaH(s0a, &ah[mi][ks * 4], &bh0[ks * 2]);
                    mmaH(s1a, &ah[mi][ks * 4], &bh1[ks * 2]);
                    mmaH(s0b, &ah[mi][(ks + 2) * 4], &bh0[(ks + 2) * 2]);
                    mmaH(s1b, &ah[mi][(ks + 2) * 4], &bh1[(ks + 2) * 2]);
                }
                sah[mi][0] = packH(fmaxf(s0a[0] + s0b[0], 0.0f), fmaxf(s0a[1] + s0b[1], 0.0f));
                sah[mi][1] = packH(fmaxf(s0a[2] + s0b[2], 0.0f), fmaxf(s0a[3] + s0b[3], 0.0f));
                sah[mi][2] = packH(fmaxf(s1a[0] + s1b[0], 0.0f), fmaxf(s1a[1] + s1b[1], 0.0f));
                sah[mi][3] = packH(fmaxf(s1a[2] + s1b[2], 0.0f), fmaxf(s1a[3] + s1b[3], 0.0f));
            }

            // ---- stage 2: load V frags once, use for both m-tiles ----
            const int vrow = j * 16 + (b_quad & 1) * 8 + b_r;
            uint32_t bvh[4][4];
            #pragma unroll
            for (int np = 0; np < 4; np++) {
                const int col = np * 16 + (b_quad >> 1) * 8;
                ldsm_x4t(bvh[np], smem_u32(&VH[vrow * PAD + col]));
            }
            #pragma unroll
            for (int mi = 0; mi < 2; mi++)
                #pragma unroll
                for (int np = 0; np < 4; np++) {
                    mmaH(oacc[mi][2 * np],     sah[mi], &bvh[np][0]);
                    mmaH(oacc[mi][2 * np + 1], sah[mi], &bvh[np][2]);
                }
        }
        __syncthreads();
    }

    // ---- epilogue ----
    #pragma unroll
    for (int mi = 0; mi < 2; mi++)
        #pragma unroll
        for (int nt2 = 0; nt2 < 8; nt2++) {
            const int row = w * 32 + mi * 16 + g;
            float2 v0 = {oacc[mi][nt2][0], oacc[mi][nt2][1]};
            float2 v1 = {oacc[mi][nt2][2], oacc[mi][nt2][3]};
            *(float2*)&o_g[(size_t)row * C_DIM + nt2 * 8 + 2 * tq] = v0;
            *(float2*)&o_g[(size_t)(row + 8) * C_DIM + nt2 * 8 + 2 * tq] = v1;
        }
}

// ---------------------------------------------------------------------------
extern "C" void kernel_launch(void* const* d_in, const int* in_sizes, int n_in,
                              void* d_out, int out_size) {
    const float* x1 = (const float*)d_in[0];
    const float* x2 = (const float*)d_in[1];
    const float* w1 = (const float*)d_in[2];
    const float* w2 = (const float*)d_in[3];
    float* out = (float*)d_out;

    (void)cudaFuncSetAttribute(attn_kernel,
                               cudaFuncAttributeMaxDynamicSharedMemorySize, ATTN_SMEM);
    (void)cudaFuncSetAttribute(kv_gemm,
                               cudaFuncAttributeMaxDynamicSharedMemorySize, KV_SMEM);

    __half *xh0, *wh0;
    (void)cudaGetSymbolAddress((void**)&xh0, g_xh);
    (void)cudaGetSymbolAddress((void**)&wh0, g_wh);

    split_all<<<(TOT4 + 255) / 256, 256>>>(x1, x2, w1, w2, xh0, wh0);

    dim3 g1(KVN / 128, M_TOT / 128, 2);
    kv_gemm<<<g1, 256, KV_SMEM>>>(0);

    dim3 g2(NSEQ / 256, NB * NHEADS, 2);   // (4, 64, 2)
    attn_kernel<<<g2, 256, ATTN_SMEM>>>(x1, x2, out);
}

// round 13
// speedup vs baseline: 1.1948x; 1.1948x over previous
#include <cuda_runtime.h>
#include <cuda_fp16.h>
#include <cstdint>

constexpr int C_DIM  = 512;
constexpr int NHEADS = 8;
constexpr int HD     = 64;
constexpr int NB     = 8;
constexpr int NSEQ   = 1024;
constexpr int M_TOT  = NB * NSEQ;     // 8192
constexpr int KVN    = 2 * C_DIM;     // 1024
constexpr float SCALE = 0.125f;

// fp16 planes: kv result, converted inputs
__device__ __half g_kvh[2][(size_t)M_TOT * KVN];
__device__ __half g_xh[2][(size_t)M_TOT * C_DIM];
__device__ __half g_wh[2][(size_t)C_DIM * KVN];

// ---------------------------------------------------------------------------
__device__ __forceinline__ uint32_t smem_u32(const void* p) {
    return (uint32_t)__cvta_generic_to_shared(p);
}
__device__ __forceinline__ void ldsm_x4(uint32_t* r, uint32_t a) {
    asm volatile("ldmatrix.sync.aligned.m8n8.x4.shared.b16 {%0,%1,%2,%3}, [%4];"
                 : "=r"(r[0]), "=r"(r[1]), "=r"(r[2]), "=r"(r[3]) : "r"(a));
}
__device__ __forceinline__ void ldsm_x4t(uint32_t* r, uint32_t a) {
    asm volatile("ldmatrix.sync.aligned.m8n8.x4.trans.shared.b16 {%0,%1,%2,%3}, [%4];"
                 : "=r"(r[0]), "=r"(r[1]), "=r"(r[2]), "=r"(r[3]) : "r"(a));
}
__device__ __forceinline__ void mmaH(float* c, const uint32_t* a, const uint32_t* b) {
    asm volatile("mma.sync.aligned.m16n8k16.row.col.f32.f16.f16.f32 "
                 "{%0,%1,%2,%3}, {%4,%5,%6,%7}, {%8,%9}, {%0,%1,%2,%3};"
                 : "+f"(c[0]), "+f"(c[1]), "+f"(c[2]), "+f"(c[3])
                 : "r"(a[0]), "r"(a[1]), "r"(a[2]), "r"(a[3]), "r"(b[0]), "r"(b[1]));
}
__device__ __forceinline__ uint32_t packH(float x0, float x1) {
    __half2 h = __floats2half2_rn(x0, x1);
    return *reinterpret_cast<uint32_t*>(&h);
}
__device__ __forceinline__ void cp16(uint32_t s, const void* g) {
    asm volatile("cp.async.cg.shared.global [%0], [%1], 16;" :: "r"(s), "l"(g));
}
__device__ __forceinline__ void cp_commit() { asm volatile("cp.async.commit_group;"); }
__device__ __forceinline__ void cp_wait0()  { asm volatile("cp.async.wait_group 0;"); }

// ---------------------------------------------------------------------------
// Kernel 0: convert x1/x2/w1/w2 -> fp16 planes.
// ---------------------------------------------------------------------------
constexpr int XN4 = M_TOT * C_DIM / 4;
constexpr int WN4 = C_DIM * KVN / 4;
constexpr int TOT4 = 2 * XN4 + 2 * WN4;

__global__ __launch_bounds__(256) void split_all(const float* __restrict__ x1,
                                                 const float* __restrict__ x2,
                                                 const float* __restrict__ w1,
                                                 const float* __restrict__ w2,
                                                 __half* __restrict__ xh,
                                                 __half* __restrict__ wh) {
    const int i = blockIdx.x * blockDim.x + threadIdx.x;
    if (i >= TOT4) return;
    const float* s;
    __half* d;
    size_t off;
    if (i < XN4)                { s = x1; d = xh;                                off = i; }
    else if (i < 2 * XN4)       { s = x2; d = xh + (size_t)M_TOT * C_DIM;        off = i - XN4; }
    else if (i < 2 * XN4 + WN4) { s = w1; d = wh;                                off = i - 2 * XN4; }
    else                        { s = w2; d = wh + (size_t)C_DIM * KVN;          off = i - 2 * XN4 - WN4; }
    const float4 v = *(const float4*)&s[off * 4];
    uint2 hv = {packH(v.x, v.y), packH(v.z, v.w)};
    *(uint2*)&d[off * 4] = hv;
}

// ---------------------------------------------------------------------------
// Kernel 1: kv = x @ W, pure fp16. NOW 2 CTAs/SM (regs capped at 128).
// 128x128 CTA tile, K-step 32, warp tile 64x32, cp.async 2-stage.
// ---------------------------------------------------------------------------
constexpr int XPAD = 40;
constexpr int WPAD = 136;
constexpr int XT = 128 * XPAD;
constexpr int WT = 32 * WPAD;
constexpr int KV_SMEM = (2 * XT + 2 * WT) * 2;   // 37888 B

__global__ __launch_bounds__(256, 2) void kv_gemm(int dummy) {
    extern __shared__ __half ksm[];
    const int br = blockIdx.z;
    const __half* __restrict__ XH_g = g_xh[br];
    const __half* __restrict__ WH_g = g_wh[br];
    __half* __restrict__ Oh = g_kvh[br];

    const int t    = threadIdx.x;
    const int w    = t >> 5;
    const int lane = t & 31;
    const int g    = lane >> 2;
    const int tq   = lane & 3;
    const int wm   = w >> 2;
    const int wn   = w & 3;
    const int m0   = blockIdx.y * 128;
    const int n0   = blockIdx.x * 128;

    const int a_row = wm * 64 + (lane & 7) + ((lane >> 3) & 1) * 8;
    const int a_col = ((lane >> 4) & 1) * 8;
    const int b_quad = lane >> 3;
    const int b_r    = lane & 7;

    const int xr0 = (t + 0)   >> 2, xc0 = ((t + 0)   & 3) * 8;
    const int xr1 = (t + 256) >> 2, xc1 = ((t + 256) & 3) * 8;
    const int wr0 = (t + 0)   >> 4, wc0 = ((t + 0)   & 15) * 8;
    const int wr1 = (t + 256) >> 4, wc1 = ((t + 256) & 15) * 8;

    auto issue = [&](int k0, int p) {
        __half* XH = ksm + p * XT;
        __half* WH = ksm + 2 * XT + p * WT;
        cp16(smem_u32(&XH[xr0 * XPAD + xc0]), &XH_g[(size_t)(m0 + xr0) * C_DIM + k0 + xc0]);
        cp16(smem_u32(&XH[xr1 * XPAD + xc1]), &XH_g[(size_t)(m0 + xr1) * C_DIM + k0 + xc1]);
        cp16(smem_u32(&WH[wr0 * WPAD + wc0]), &WH_g[(size_t)(k0 + wr0) * KVN + n0 + wc0]);
        cp16(smem_u32(&WH[wr1 * WPAD + wc1]), &WH_g[(size_t)(k0 + wr1) * KVN + n0 + wc1]);
        cp_commit();
    };

    float acc[4][4][4] = {};

    issue(0, 0);
    for (int ki = 0; ki < 16; ki++) {
        cp_wait0();
        __syncthreads();
        if (ki + 1 < 16) issue((ki + 1) * 32, (ki + 1) & 1);
        const int p = ki & 1;
        const __half* XH = ksm + p * XT;
        const __half* WH = ksm + 2 * XT + p * WT;

        #pragma unroll
        for (int ks = 0; ks < 2; ks++) {
            uint32_t ah[4][4];
            #pragma unroll
            for (int mi = 0; mi < 4; mi++) {
                const int addr = (a_row + mi * 16) * XPAD + ks * 16 + a_col;
                ldsm_x4(ah[mi], smem_u32(&XH[addr]));
            }
            uint32_t bh[2][4];
            #pragma unroll
            for (int nip = 0; nip < 2; nip++) {
                const int row = ks * 16 + (b_quad & 1) * 8 + b_r;
                const int col = wn * 32 + nip * 16 + (b_quad >> 1) * 8;
                ldsm_x4t(bh[nip], smem_u32(&WH[row * WPAD + col]));
            }
            #pragma unroll
            for (int mi = 0; mi < 4; mi++)
                #pragma unroll
                for (int nn = 0; nn < 4; nn++)
                    mmaH(acc[mi][nn], ah[mi], &bh[nn >> 1][(nn & 1) * 2]);
        }
        __syncthreads();
    }

    #pragma unroll
    for (int mi = 0; mi < 4; mi++)
        #pragma unroll
        for (int nn = 0; nn < 4; nn++) {
            const int row = m0 + wm * 64 + mi * 16 + g;
            const int col = n0 + wn * 32 + nn * 8 + 2 * tq;
            *(uint32_t*)&Oh[(size_t)row * KVN + col] = packH(acc[mi][nn][0], acc[mi][nn][1]);
            *(uint32_t*)&Oh[(size_t)(row + 8) * KVN + col] = packH(acc[mi][nn][2], acc[mi][nn][3]);
        }
}

// ---------------------------------------------------------------------------
// Kernel 2: fused cross attention (round-11 config: 16 q-rows/warp, 2 CTAs/SM).
// smem: QH + 2 x (KH, VH) = 5 planes of 128x88 fp16 = 112640 B.
// ---------------------------------------------------------------------------
constexpr int PAD = 88;
constexpr int TILE_ELE = 128 * PAD;
constexpr int ATTN_SMEM = 5 * TILE_ELE * 2;   // 112640 B

__global__ __launch_bounds__(256, 2) void attn_kernel(const float* __restrict__ x1,
                                                      const float* __restrict__ x2,
                                                      float* __restrict__ out) {
    extern __shared__ __half smb[];
    __half* QH = smb;

    const int br = blockIdx.z;
    const int bh = blockIdx.y;
    const int bb = bh >> 3;
    const int hh = bh & 7;
    const int qt = blockIdx.x;

    const float* __restrict__ q_g = (br ? x2 : x1)
        + (size_t)bb * NSEQ * C_DIM + (size_t)qt * 128 * C_DIM + hh * HD;
    const __half* __restrict__ KHg = g_kvh[1 - br];
    const __half* __restrict__ VHg = g_kvh[br];
    float* __restrict__ o_g = out + (size_t)br * NB * NSEQ * C_DIM
        + (size_t)bb * NSEQ * C_DIM + (size_t)qt * 128 * C_DIM + hh * HD;

    const int tid  = threadIdx.x;
    const int w    = tid >> 5;
    const int lane = tid & 31;
    const int g    = lane >> 2;
    const int tq   = lane & 3;

    const size_t kv_row0 = (size_t)bb * NSEQ;
    const int kcol = hh * HD;
    const int vcol = C_DIM + hh * HD;

    int cm[4], cd[4];
    #pragma unroll
    for (int l = 0; l < 4; l++) {
        const int c = tid + l * 256;
        cm[l] = c >> 3;
        cd[l] = (c & 7) * 8;
    }

    auto issue = [&](int mt, int p) {
        __half* KH = smb + (1 + p * 2 + 0) * TILE_ELE;
        __half* VH = smb + (1 + p * 2 + 1) * TILE_ELE;
        const size_t rbase = kv_row0 + (size_t)mt * 128;
        #pragma unroll
        for (int l = 0; l < 4; l++) {
            const size_t gidx = (rbase + cm[l]) * KVN;
            const int so = cm[l] * PAD + cd[l];
            cp16(smem_u32(&KH[so]), &KHg[gidx + kcol + cd[l]]);
            cp16(smem_u32(&VH[so]), &VHg[gidx + vcol + cd[l]]);
        }
        cp_commit();
    };

    // ---- prologue: issue tile 0; load + scale + round Q to fp16 ----
    issue(0, 0);
    #pragma unroll
    for (int l = 0; l < 8; l++) {
        const int c   = tid + l * 256;
        const int row = c >> 4;
        const int c4  = (c & 15) * 4;
        float4 q4 = *(const float4*)&q_g[(size_t)row * C_DIM + c4];
        uint2 hv = {packH(q4.x * SCALE, q4.y * SCALE), packH(q4.z * SCALE, q4.w * SCALE)};
        *(uint2*)&QH[row * PAD + c4] = hv;
    }
    __syncthreads();

    // loop-invariant Q fragments
    const int a_row_off = (lane & 7) + ((lane >> 3) & 1) * 8;
    const int a_col_off = ((lane >> 4) & 1) * 8;
    uint32_t ah[16];
    #pragma unroll
    for (int ks = 0; ks < 4; ks++) {
        const int arow = w * 16 + a_row_off;
        const int acol = ks * 16 + a_col_off;
        ldsm_x4(&ah[ks * 4], smem_u32(&QH[arow * PAD + acol]));
    }

    float oacc[8][4] = {};
    const int b_quad = lane >> 3;
    const int b_r    = lane & 7;

    for (int mt = 0; mt < 8; mt++) {
        cp_wait0();
        __syncthreads();
        if (mt + 1 < 8) issue(mt + 1, (mt + 1) & 1);

        const int p = mt & 1;
        const __half* KH = smb + (1 + p * 2 + 0) * TILE_ELE;
        const __half* VH = smb + (1 + p * 2 + 1) * TILE_ELE;

        #pragma unroll
        for (int j = 0; j < 8; j++) {
            const int bcol  = b_quad * 8;
            const int brow0 = (2 * j + 0) * 8 + b_r;
            const int brow1 = (2 * j + 1) * 8 + b_r;
            uint32_t bh0[8], bh1[8];
            ldsm_x4(&bh0[0], smem_u32(&KH[brow0 * PAD + bcol]));
            ldsm_x4(&bh0[4], smem_u32(&KH[brow0 * PAD + 32 + bcol]));
            ldsm_x4(&bh1[0], smem_u32(&KH[brow1 * PAD + bcol]));
            ldsm_x4(&bh1[4], smem_u32(&KH[brow1 * PAD + 32 + bcol]));

            // ---- stage 1: 4 independent chains (2 halves x 2 k-splits) ----
            float s0a[4] = {}, s0b[4] = {}, s1a[4] = {}, s1b[4] = {};
            #pragma unroll
            for (int ks = 0; ks < 2; ks++) {
                mmaH(s0a, &ah[ks * 4], &bh0[ks * 2]);
                mmaH(s1a, &ah[ks * 4], &bh1[ks * 2]);
                mmaH(s0b, &ah[(ks + 2) * 4], &bh0[(ks + 2) * 2]);
                mmaH(s1b, &ah[(ks + 2) * 4], &bh1[(ks + 2) * 2]);
            }

            // relu (scale folded into q), round S to fp16 A-fragment
            uint32_t sah[4];
            sah[0] = packH(fmaxf(s0a[0] + s0b[0], 0.0f), fmaxf(s0a[1] + s0b[1], 0.0f));
            sah[1] = packH(fmaxf(s0a[2] + s0b[2], 0.0f), fmaxf(s0a[3] + s0b[3], 0.0f));
            sah[2] = packH(fmaxf(s1a[0] + s1b[0], 0.0f), fmaxf(s1a[1] + s1b[1], 0.0f));
            sah[3] = packH(fmaxf(s1a[2] + s1b[2], 0.0f), fmaxf(s1a[3] + s1b[3], 0.0f));

            // ---- stage 2: O += S . v  (8 independent accumulators) ----
            const int vrow = j * 16 + (b_quad & 1) * 8 + b_r;
            #pragma unroll
            for (int np = 0; np < 4; np++) {
                const int col = np * 16 + (b_quad >> 1) * 8;
                uint32_t bvh[4];
                ldsm_x4t(bvh, smem_u32(&VH[vrow * PAD + col]));
                mmaH(oacc[2 * np],     sah, &bvh[0]);
                mmaH(oacc[2 * np + 1], sah, &bvh[2]);
            }
        }
        __syncthreads();
    }

    #pragma unroll
    for (int nt2 = 0; nt2 < 8; nt2++) {
        float2 v0 = {oacc[nt2][0], oacc[nt2][1]};
        float2 v1 = {oacc[nt2][2], oacc[nt2][3]};
        *(float2*)&o_g[(size_t)(w * 16 + g) * C_DIM + nt2 * 8 + 2 * tq] = v0;
        *(float2*)&o_g[(size_t)(w * 16 + g + 8) * C_DIM + nt2 * 8 + 2 * tq] = v1;
    }
}

// ---------------------------------------------------------------------------
extern "C" void kernel_launch(void* const* d_in, const int* in_sizes, int n_in,
                              void* d_out, int out_size) {
    const float* x1 = (const float*)d_in[0];
    const float* x2 = (const float*)d_in[1];
    const float* w1 = (const float*)d_in[2];
    const float* w2 = (const float*)d_in[3];
    float* out = (float*)d_out;

    (void)cudaFuncSetAttribute(attn_kernel,
                               cudaFuncAttributeMaxDynamicSharedMemorySize, ATTN_SMEM);
    (void)cudaFuncSetAttribute(kv_gemm,
                               cudaFuncAttributeMaxDynamicSharedMemorySize, KV_SMEM);

    __half *xh0, *wh0;
    (void)cudaGetSymbolAddress((void**)&xh0, g_xh);
    (void)cudaGetSymbolAddress((void**)&wh0, g_wh);

    split_all<<<(TOT4 + 255) / 256, 256>>>(x1, x2, w1, w2, xh0, wh0);

    dim3 g1(KVN / 128, M_TOT / 128, 2);
    kv_gemm<<<g1, 256, KV_SMEM>>>(0);

    dim3 g2(NSEQ / 128, NB * NHEADS, 2);
    attn_kernel<<<g2, 256, ATTN_SMEM>>>(x1, x2, out);
}

// round 15
// speedup vs baseline: 1.2060x; 1.0094x over previous
#include <cuda_runtime.h>
#include <cuda_fp16.h>
#include <cstdint>

constexpr int C_DIM  = 512;
constexpr int NHEADS = 8;
constexpr int HD     = 64;
constexpr int NB     = 8;
constexpr int NSEQ   = 1024;
constexpr int M_TOT  = NB * NSEQ;     // 8192
constexpr int KVN    = 2 * C_DIM;     // 1024
constexpr float SCALE = 0.125f;

// fp16 planes: kv result, converted W
__device__ __half g_kvh[2][(size_t)M_TOT * KVN];
__device__ __half g_wh[2][(size_t)C_DIM * KVN];

// ---------------------------------------------------------------------------
__device__ __forceinline__ uint32_t smem_u32(const void* p) {
    return (uint32_t)__cvta_generic_to_shared(p);
}
__device__ __forceinline__ void ldsm_x4(uint32_t* r, uint32_t a) {
    asm volatile("ldmatrix.sync.aligned.m8n8.x4.shared.b16 {%0,%1,%2,%3}, [%4];"
                 : "=r"(r[0]), "=r"(r[1]), "=r"(r[2]), "=r"(r[3]) : "r"(a));
}
__device__ __forceinline__ void ldsm_x4t(uint32_t* r, uint32_t a) {
    asm volatile("ldmatrix.sync.aligned.m8n8.x4.trans.shared.b16 {%0,%1,%2,%3}, [%4];"
                 : "=r"(r[0]), "=r"(r[1]), "=r"(r[2]), "=r"(r[3]) : "r"(a));
}
__device__ __forceinline__ void mmaH(float* c, const uint32_t* a, const uint32_t* b) {
    asm volatile("mma.sync.aligned.m16n8k16.row.col.f32.f16.f16.f32 "
                 "{%0,%1,%2,%3}, {%4,%5,%6,%7}, {%8,%9}, {%0,%1,%2,%3};"
                 : "+f"(c[0]), "+f"(c[1]), "+f"(c[2]), "+f"(c[3])
                 : "r"(a[0]), "r"(a[1]), "r"(a[2]), "r"(a[3]), "r"(b[0]), "r"(b[1]));
}
__device__ __forceinline__ uint32_t packH(float x0, float x1) {
    __half2 h = __floats2half2_rn(x0, x1);
    return *reinterpret_cast<uint32_t*>(&h);
}
__device__ __forceinline__ uint32_t hmax2z(uint32_t x) {
    uint32_t r;
    asm("max.f16x2 %0, %1, %2;" : "=r"(r) : "r"(x), "r"(0u));
    return r;
}
__device__ __forceinline__ void cp16(uint32_t s, const void* g) {
    asm volatile("cp.async.cg.shared.global [%0], [%1], 16;" :: "r"(s), "l"(g));
}
__device__ __forceinline__ void cp_commit() { asm volatile("cp.async.commit_group;"); }
__device__ __forceinline__ void cp_wait0()  { asm volatile("cp.async.wait_group 0;"); }

// ---------------------------------------------------------------------------
// Kernel 0: convert w1/w2 -> fp16 (x is converted on-the-fly inside kv_gemm).
// ---------------------------------------------------------------------------
constexpr int WN4 = C_DIM * KVN / 4;      // 131,072
constexpr int WTOT4 = 2 * WN4;

__global__ __launch_bounds__(256) void split_w(const float* __restrict__ w1,
                                               const float* __restrict__ w2,
                                               __half* __restrict__ wh) {
    const int i = blockIdx.x * blockDim.x + threadIdx.x;
    if (i >= WTOT4) return;
    const float* s = (i < WN4) ? w1 : w2;
    const size_t off = (i < WN4) ? (size_t)i : (size_t)(i - WN4);
    __half* d = wh + ((i < WN4) ? 0 : (size_t)C_DIM * KVN);
    const float4 v = *(const float4*)&s[off * 4];
    uint2 hv = {packH(v.x, v.y), packH(v.z, v.w)};
    *(uint2*)&d[off * 4] = hv;
}

// ---------------------------------------------------------------------------
// Kernel 1: kv = x @ W, pure fp16, 2 CTAs/SM.
// X read as fp32 and converted during STS (no x prepass). W via cp.async.
// 128x128 CTA tile, K-step 32, warp tile 64x32.
// ---------------------------------------------------------------------------
constexpr int XPAD = 40;
constexpr int WPAD = 136;
constexpr int XT = 128 * XPAD;
constexpr int WT = 32 * WPAD;
constexpr int KV_SMEM = (2 * XT + 2 * WT) * 2;   // 37888 B

__global__ __launch_bounds__(256, 2) void kv_gemm(const float* __restrict__ x1,
                                                  const float* __restrict__ x2) {
    extern __shared__ __half ksm[];
    const int br = blockIdx.z;
    const float* __restrict__ Xg = br ? x2 : x1;
    const __half* __restrict__ WH_g = g_wh[br];
    __half* __restrict__ Oh = g_kvh[br];

    const int t    = threadIdx.x;
    const int w    = t >> 5;
    const int lane = t & 31;
    const int g    = lane >> 2;
    const int tq   = lane & 3;
    const int wm   = w >> 2;
    const int wn   = w & 3;
    const int m0   = blockIdx.y * 128;
    const int n0   = blockIdx.x * 128;

    const int a_row = wm * 64 + (lane & 7) + ((lane >> 3) & 1) * 8;
    const int a_col = ((lane >> 4) & 1) * 8;
    const int b_quad = lane >> 3;
    const int b_r    = lane & 7;

    // X chunk mapping: 1024 float4 chunks (128 rows x 8 chunks), 4 per thread
    int xrow[4], xcol[4];
    #pragma unroll
    for (int l = 0; l < 4; l++) {
        const int c = t + l * 256;
        xrow[l] = c >> 3;
        xcol[l] = (c & 7) * 4;
    }
    const int wr0 = (t + 0)   >> 4, wc0 = ((t + 0)   & 15) * 8;
    const int wr1 = (t + 256) >> 4, wc1 = ((t + 256) & 15) * 8;

    auto issueW = [&](int k0, int p) {
        __half* WH = ksm + 2 * XT + p * WT;
        cp16(smem_u32(&WH[wr0 * WPAD + wc0]), &WH_g[(size_t)(k0 + wr0) * KVN + n0 + wc0]);
        cp16(smem_u32(&WH[wr1 * WPAD + wc1]), &WH_g[(size_t)(k0 + wr1) * KVN + n0 + wc1]);
        cp_commit();
    };

    float acc[4][4][4] = {};
    float4 xa[4];

    // prefetch X(k0=0) + issue W(0)
    #pragma unroll
    for (int l = 0; l < 4; l++)
        xa[l] = *(const float4*)&Xg[(size_t)(m0 + xrow[l]) * C_DIM + xcol[l]];
    issueW(0, 0);

    for (int ki = 0; ki < 16; ki++) {
        cp_wait0();
        __syncthreads();          // W(ki) visible; prior reads of buffers p done
        const int p = ki & 1;
        __half* XH = ksm + p * XT;

        // convert + store X tile
        #pragma unroll
        for (int l = 0; l < 4; l++) {
            uint2 hv = {packH(xa[l].x, xa[l].y), packH(xa[l].z, xa[l].w)};
            *(uint2*)&XH[xrow[l] * XPAD + xcol[l]] = hv;
        }
        if (ki + 1 < 16) {
            issueW((ki + 1) * 32, p ^ 1);
            #pragma unroll
            for (int l = 0; l < 4; l++)
                xa[l] = *(const float4*)&Xg[(size_t)(m0 + xrow[l]) * C_DIM + (ki + 1) * 32 + xcol[l]];
        }
        __syncthreads();          // X STS visible

        const __half* XHc = ksm + p * XT;
        const __half* WHc = ksm + 2 * XT + p * WT;
        #pragma unroll
        for (int ks = 0; ks < 2; ks++) {
            uint32_t ah[4][4];
            #pragma unroll
            for (int mi = 0; mi < 4; mi++) {
                const int addr = (a_row + mi * 16) * XPAD + ks * 16 + a_col;
                ldsm_x4(ah[mi], smem_u32(&XHc[addr]));
            }
            uint32_t bh[2][4];
            #pragma unroll
            for (int nip = 0; nip < 2; nip++) {
                const int row = ks * 16 + (b_quad & 1) * 8 + b_r;
                const int col = wn * 32 + nip * 16 + (b_quad >> 1) * 8;
                ldsm_x4t(bh[nip], smem_u32(&WHc[row * WPAD + col]));
            }
            #pragma unroll
            for (int mi = 0; mi < 4; mi++)
                #pragma unroll
                for (int nn = 0; nn < 4; nn++)
                    mmaH(acc[mi][nn], ah[mi], &bh[nn >> 1][(nn & 1) * 2]);
        }
    }

    #pragma unroll
    for (int mi = 0; mi < 4; mi++)
        #pragma unroll
        for (int nn = 0; nn < 4; nn++) {
            const int row = m0 + wm * 64 + mi * 16 + g;
            const int col = n0 + wn * 32 + nn * 8 + 2 * tq;
            *(uint32_t*)&Oh[(size_t)row * KVN + col] = packH(acc[mi][nn][0], acc[mi][nn][1]);
            *(uint32_t*)&Oh[(size_t)(row + 8) * KVN + col] = packH(acc[mi][nn][2], acc[mi][nn][3]);
        }
}

// ---------------------------------------------------------------------------
// Kernel 2: fused cross attention (16 q-rows/warp, 2 CTAs/SM; hmax2 relu).
// smem: QH + 2 x (KH, VH) = 5 planes of 128x88 fp16 = 112640 B.
// ---------------------------------------------------------------------------
constexpr int PAD = 88;
constexpr int TILE_ELE = 128 * PAD;
constexpr int ATTN_SMEM = 5 * TILE_ELE * 2;   // 112640 B

__global__ __launch_bounds__(256, 2) void attn_kernel(const float* __restrict__ x1,
                                                      const float* __restrict__ x2,
                                                      float* __restrict__ out) {
    extern __shared__ __half smb[];
    __half* QH = smb;

    const int br = blockIdx.z;
    const int bh = blockIdx.y;
    const int bb = bh >> 3;
    const int hh = bh & 7;
    const int qt = blockIdx.x;

    const float* __restrict__ q_g = (br ? x2 : x1)
        + (size_t)bb * NSEQ * C_DIM + (size_t)qt * 128 * C_DIM + hh * HD;
    const __half* __restrict__ KHg = g_kvh[1 - br];
    const __half* __restrict__ VHg = g_kvh[br];
    float* __restrict__ o_g = out + (size_t)br * NB * NSEQ * C_DIM
        + (size_t)bb * NSEQ * C_DIM + (size_t)qt * 128 * C_DIM + hh * HD;

    const int tid  = threadIdx.x;
    const int w    = tid >> 5;
    const int lane = tid & 31;
    const int g    = lane >> 2;
    const int tq   = lane & 3;

    const size_t kv_row0 = (size_t)bb * NSEQ;
    const int kcol = hh * HD;
    const int vcol = C_DIM + hh * HD;

    int cm[4], cd[4];
    #pragma unroll
    for (int l = 0; l < 4; l++) {
        const int c = tid + l * 256;
        cm[l] = c >> 3;
        cd[l] = (c & 7) * 8;
    }

    auto issue = [&](int mt, int p) {
        __half* KH = smb + (1 + p * 2 + 0) * TILE_ELE;
        __half* VH = smb + (1 + p * 2 + 1) * TILE_ELE;
        const size_t rbase = kv_row0 + (size_t)mt * 128;
        #pragma unroll
        for (int l = 0; l < 4; l++) {
            const size_t gidx = (rbase + cm[l]) * KVN;
            const int so = cm[l] * PAD + cd[l];
            cp16(smem_u32(&KH[so]), &KHg[gidx + kcol + cd[l]]);
            cp16(smem_u32(&VH[so]), &VHg[gidx + vcol + cd[l]]);
        }
        cp_commit();
    };

    // ---- prologue: issue tile 0; load + scale + round Q to fp16 ----
    issue(0, 0);
    #pragma unroll
    for (int l = 0; l < 8; l++) {
        const int c   = tid + l * 256;
        const int row = c >> 4;
        const int c4  = (c & 15) * 4;
        float4 q4 = *(const float4*)&q_g[(size_t)row * C_DIM + c4];
        uint2 hv = {packH(q4.x * SCALE, q4.y * SCALE), packH(q4.z * SCALE, q4.w * SCALE)};
        *(uint2*)&QH[row * PAD + c4] = hv;
    }
    __syncthreads();

    // loop-invariant Q fragments
    const int a_row_off = (lane & 7) + ((lane >> 3) & 1) * 8;
    const int a_col_off = ((lane >> 4) & 1) * 8;
    uint32_t ah[16];
    #pragma unroll
    for (int ks = 0; ks < 4; ks++) {
        const int arow = w * 16 + a_row_off;
        const int acol = ks * 16 + a_col_off;
        ldsm_x4(&ah[ks * 4], smem_u32(&QH[arow * PAD + acol]));
    }

    float oacc[8][4] = {};
    const int b_quad = lane >> 3;
    const int b_r    = lane & 7;

    for (int mt = 0; mt < 8; mt++) {
        cp_wait0();
        __syncthreads();
        if (mt + 1 < 8) issue(mt + 1, (mt + 1) & 1);

        const int p = mt & 1;
        const __half* KH = smb + (1 + p * 2 + 0) * TILE_ELE;
        const __half* VH = smb + (1 + p * 2 + 1) * TILE_ELE;

        #pragma unroll
        for (int j = 0; j < 8; j++) {
            const int bcol  = b_quad * 8;
            const int brow0 = (2 * j + 0) * 8 + b_r;
            const int brow1 = (2 * j + 1) * 8 + b_r;
            uint32_t bh0[8], bh1[8];
            ldsm_x4(&bh0[0], smem_u32(&KH[brow0 * PAD + bcol]));
            ldsm_x4(&bh0[4], smem_u32(&KH[brow0 * PAD + 32 + bcol]));
            ldsm_x4(&bh1[0], smem_u32(&KH[brow1 * PAD + bcol]));
            ldsm_x4(&bh1[4], smem_u32(&KH[brow1 * PAD + 32 + bcol]));

            // ---- stage 1: 4 independent chains (2 halves x 2 k-splits) ----
            float s0a[4] = {}, s0b[4] = {}, s1a[4] = {}, s1b[4] = {};
            #pragma unroll
            for (int ks = 0; ks < 2; ks++) {
                mmaH(s0a, &ah[ks * 4], &bh0[ks * 2]);
                mmaH(s1a, &ah[ks * 4], &bh1[ks * 2]);
                mmaH(s0b, &ah[(ks + 2) * 4], &bh0[(ks + 2) * 2]);
                mmaH(s1b, &ah[(ks + 2) * 4], &bh1[(ks + 2) * 2]);
            }

            // pack to fp16, relu via max.f16x2 (scale folded into q)
            uint32_t sah[4];
            sah[0] = hmax2z(packH(s0a[0] + s0b[0], s0a[1] + s0b[1]));
            sah[1] = hmax2z(packH(s0a[2] + s0b[2], s0a[3] + s0b[3]));
            sah[2] = hmax2z(packH(s1a[0] + s1b[0], s1a[1] + s1b[1]));
            sah[3] = hmax2z(packH(s1a[2] + s1b[2], s1a[3] + s1b[3]));

            // ---- stage 2: O += S . v  (8 independent accumulators) ----
            const int vrow = j * 16 + (b_quad & 1) * 8 + b_r;
            #pragma unroll
            for (int np = 0; np < 4; np++) {
                const int col = np * 16 + (b_quad >> 1) * 8;
                uint32_t bvh[4];
                ldsm_x4t(bvh, smem_u32(&VH[vrow * PAD + col]));
                mmaH(oacc[2 * np],     sah, &bvh[0]);
                mmaH(oacc[2 * np + 1], sah, &bvh[2]);
            }
        }
        __syncthreads();
    }

    #pragma unroll
    for (int nt2 = 0; nt2 < 8; nt2++) {
        float2 v0 = {oacc[nt2][0], oacc[nt2][1]};
        float2 v1 = {oacc[nt2][2], oacc[nt2][3]};
        *(float2*)&o_g[(size_t)(w * 16 + g) * C_DIM + nt2 * 8 + 2 * tq] = v0;
        *(float2*)&o_g[(size_t)(w * 16 + g + 8) * C_DIM + nt2 * 8 + 2 * tq] = v1;
    }
}

// ---------------------------------------------------------------------------
extern "C" void kernel_launch(void* const* d_in, const int* in_sizes, int n_in,
                              void* d_out, int out_size) {
    const float* x1 = (const float*)d_in[0];
    const float* x2 = (const float*)d_in[1];
    const float* w1 = (const float*)d_in[2];
    const float* w2 = (const float*)d_in[3];
    float* out = (float*)d_out;

    (void)cudaFuncSetAttribute(attn_kernel,
                               cudaFuncAttributeMaxDynamicSharedMemorySize, ATTN_SMEM);
    (void)cudaFuncSetAttribute(kv_gemm,
                               cudaFuncAttributeMaxDynamicSharedMemorySize, KV_SMEM);

    __half* wh0;
    (void)cudaGetSymbolAddress((void**)&wh0, g_wh);

    split_w<<<(WTOT4 + 255) / 256, 256>>>(w1, w2, wh0);

    dim3 g1(KVN / 128, M_TOT / 128, 2);
    kv_gemm<<<g1, 256, KV_SMEM>>>(x1, x2);

    dim3 g2(NSEQ / 128, NB * NHEADS, 2);
    attn_kernel<<<g2, 256, ATTN_SMEM>>>(x1, x2, out);
}

// round 16
// speedup vs baseline: 1.2364x; 1.0252x over previous
#include <cuda_runtime.h>
#include <cuda_fp16.h>
#include <cstdint>

constexpr int C_DIM  = 512;
constexpr int NHEADS = 8;
constexpr int HD     = 64;
constexpr int NB     = 8;
constexpr int NSEQ   = 1024;
constexpr int M_TOT  = NB * NSEQ;     // 8192
constexpr int KVN    = 2 * C_DIM;     // 1024
constexpr float SCALE = 0.125f;

// fp16 planes: kv result, converted W
__device__ __half g_kvh[2][(size_t)M_TOT * KVN];
__device__ __half g_wh[2][(size_t)C_DIM * KVN];

// ---------------------------------------------------------------------------
__device__ __forceinline__ uint32_t smem_u32(const void* p) {
    return (uint32_t)__cvta_generic_to_shared(p);
}
__device__ __forceinline__ void ldsm_x4(uint32_t* r, uint32_t a) {
    asm volatile("ldmatrix.sync.aligned.m8n8.x4.shared.b16 {%0,%1,%2,%3}, [%4];"
                 : "=r"(r[0]), "=r"(r[1]), "=r"(r[2]), "=r"(r[3]) : "r"(a));
}
__device__ __forceinline__ void ldsm_x4t(uint32_t* r, uint32_t a) {
    asm volatile("ldmatrix.sync.aligned.m8n8.x4.trans.shared.b16 {%0,%1,%2,%3}, [%4];"
                 : "=r"(r[0]), "=r"(r[1]), "=r"(r[2]), "=r"(r[3]) : "r"(a));
}
// fp32-accum mma (stage 2, kv_gemm)
__device__ __forceinline__ void mmaH(float* c, const uint32_t* a, const uint32_t* b) {
    asm volatile("mma.sync.aligned.m16n8k16.row.col.f32.f16.f16.f32 "
                 "{%0,%1,%2,%3}, {%4,%5,%6,%7}, {%8,%9}, {%0,%1,%2,%3};"
                 : "+f"(c[0]), "+f"(c[1]), "+f"(c[2]), "+f"(c[3])
                 : "r"(a[0]), "r"(a[1]), "r"(a[2]), "r"(a[3]), "r"(b[0]), "r"(b[1]));
}
// fp16-accum mma (stage 1): D/C are 2 packed f16x2 regs; C-frag == A-frag half-pairs
__device__ __forceinline__ void mmaHf16(uint32_t* c, const uint32_t* a, const uint32_t* b) {
    asm volatile("mma.sync.aligned.m16n8k16.row.col.f16.f16.f16.f16 "
                 "{%0,%1}, {%2,%3,%4,%5}, {%6,%7}, {%0,%1};"
                 : "+r"(c[0]), "+r"(c[1])
                 : "r"(a[0]), "r"(a[1]), "r"(a[2]), "r"(a[3]), "r"(b[0]), "r"(b[1]));
}
__device__ __forceinline__ uint32_t packH(float x0, float x1) {
    __half2 h = __floats2half2_rn(x0, x1);
    return *reinterpret_cast<uint32_t*>(&h);
}
__device__ __forceinline__ uint32_t hmax2z(uint32_t x) {
    uint32_t r;
    asm("max.f16x2 %0, %1, %2;" : "=r"(r) : "r"(x), "r"(0u));
    return r;
}
__device__ __forceinline__ void cp16(uint32_t s, const void* g) {
    asm volatile("cp.async.cg.shared.global [%0], [%1], 16;" :: "r"(s), "l"(g));
}
__device__ __forceinline__ void cp_commit() { asm volatile("cp.async.commit_group;"); }
__device__ __forceinline__ void cp_wait0()  { asm volatile("cp.async.wait_group 0;"); }

// ---------------------------------------------------------------------------
// Kernel 0: convert w1/w2 -> fp16.
// ---------------------------------------------------------------------------
constexpr int WN4 = C_DIM * KVN / 4;
constexpr int WTOT4 = 2 * WN4;

__global__ __launch_bounds__(256) void split_w(const float* __restrict__ w1,
                                               const float* __restrict__ w2,
                                               __half* __restrict__ wh) {
    const int i = blockIdx.x * blockDim.x + threadIdx.x;
    if (i >= WTOT4) return;
    const float* s = (i < WN4) ? w1 : w2;
    const size_t off = (i < WN4) ? (size_t)i : (size_t)(i - WN4);
    __half* d = wh + ((i < WN4) ? 0 : (size_t)C_DIM * KVN);
    const float4 v = *(const float4*)&s[off * 4];
    uint2 hv = {packH(v.x, v.y), packH(v.z, v.w)};
    *(uint2*)&d[off * 4] = hv;
}

// ---------------------------------------------------------------------------
// Kernel 1: kv = x @ W, pure fp16, 2 CTAs/SM. X converted on the fly.
// ---------------------------------------------------------------------------
constexpr int XPAD = 40;
constexpr int WPAD = 136;
constexpr int XT = 128 * XPAD;
constexpr int WT = 32 * WPAD;
constexpr int KV_SMEM = (2 * XT + 2 * WT) * 2;   // 37888 B

__global__ __launch_bounds__(256, 2) void kv_gemm(const float* __restrict__ x1,
                                                  const float* __restrict__ x2) {
    extern __shared__ __half ksm[];
    const int br = blockIdx.z;
    const float* __restrict__ Xg = br ? x2 : x1;
    const __half* __restrict__ WH_g = g_wh[br];
    __half* __restrict__ Oh = g_kvh[br];

    const int t    = threadIdx.x;
    const int w    = t >> 5;
    const int lane = t & 31;
    const int g    = lane >> 2;
    const int tq   = lane & 3;
    const int wm   = w >> 2;
    const int wn   = w & 3;
    const int m0   = blockIdx.y * 128;
    const int n0   = blockIdx.x * 128;

    const int a_row = wm * 64 + (lane & 7) + ((lane >> 3) & 1) * 8;
    const int a_col = ((lane >> 4) & 1) * 8;
    const int b_quad = lane >> 3;
    const int b_r    = lane & 7;

    int xrow[4], xcol[4];
    #pragma unroll
    for (int l = 0; l < 4; l++) {
        const int c = t + l * 256;
        xrow[l] = c >> 3;
        xcol[l] = (c & 7) * 4;
    }
    const int wr0 = (t + 0)   >> 4, wc0 = ((t + 0)   & 15) * 8;
    const int wr1 = (t + 256) >> 4, wc1 = ((t + 256) & 15) * 8;

    auto issueW = [&](int k0, int p) {
        __half* WH = ksm + 2 * XT + p * WT;
        cp16(smem_u32(&WH[wr0 * WPAD + wc0]), &WH_g[(size_t)(k0 + wr0) * KVN + n0 + wc0]);
        cp16(smem_u32(&WH[wr1 * WPAD + wc1]), &WH_g[(size_t)(k0 + wr1) * KVN + n0 + wc1]);
        cp_commit();
    };

    float acc[4][4][4] = {};
    float4 xa[4];

    #pragma unroll
    for (int l = 0; l < 4; l++)
        xa[l] = *(const float4*)&Xg[(size_t)(m0 + xrow[l]) * C_DIM + xcol[l]];
    issueW(0, 0);

    for (int ki = 0; ki < 16; ki++) {
        cp_wait0();
        __syncthreads();
        const int p = ki & 1;
        __half* XH = ksm + p * XT;

        #pragma unroll
        for (int l = 0; l < 4; l++) {
            uint2 hv = {packH(xa[l].x, xa[l].y), packH(xa[l].z, xa[l].w)};
            *(uint2*)&XH[xrow[l] * XPAD + xcol[l]] = hv;
        }
        if (ki + 1 < 16) {
            issueW((ki + 1) * 32, p ^ 1);
            #pragma unroll
            for (int l = 0; l < 4; l++)
                xa[l] = *(const float4*)&Xg[(size_t)(m0 + xrow[l]) * C_DIM + (ki + 1) * 32 + xcol[l]];
        }
        __syncthreads();

        const __half* XHc = ksm + p * XT;
        const __half* WHc = ksm + 2 * XT + p * WT;
        #pragma unroll
        for (int ks = 0; ks < 2; ks++) {
            uint32_t ah[4][4];
            #pragma unroll
            for (int mi = 0; mi < 4; mi++) {
                const int addr = (a_row + mi * 16) * XPAD + ks * 16 + a_col;
                ldsm_x4(ah[mi], smem_u32(&XHc[addr]));
            }
            uint32_t bh[2][4];
            #pragma unroll
            for (int nip = 0; nip < 2; nip++) {
                const int row = ks * 16 + (b_quad & 1) * 8 + b_r;
                const int col = wn * 32 + nip * 16 + (b_quad >> 1) * 8;
                ldsm_x4t(bh[nip], smem_u32(&WHc[row * WPAD + col]));
            }
            #pragma unroll
            for (int mi = 0; mi < 4; mi++)
                #pragma unroll
                for (int nn = 0; nn < 4; nn++)
                    mmaH(acc[mi][nn], ah[mi], &bh[nn >> 1][(nn & 1) * 2]);
        }
    }

    #pragma unroll
    for (int mi = 0; mi < 4; mi++)
        #pragma unroll
        for (int nn = 0; nn < 4; nn++) {
            const int row = m0 + wm * 64 + mi * 16 + g;
            const int col = n0 + wn * 32 + nn * 8 + 2 * tq;
            *(uint32_t*)&Oh[(size_t)row * KVN + col] = packH(acc[mi][nn][0], acc[mi][nn][1]);
            *(uint32_t*)&Oh[(size_t)(row + 8) * KVN + col] = packH(acc[mi][nn][2], acc[mi][nn][3]);
        }
}

// ---------------------------------------------------------------------------
// Kernel 2: fused cross attention. Stage 1 accumulates in fp16 (C-frag == A-frag),
// so S needs no FADD/pack — relu via max.f16x2 on the mma outputs directly.
// 16 q-rows/warp, 2 CTAs/SM. smem: QH + 2 x (KH, VH) = 112640 B.
// ---------------------------------------------------------------------------
constexpr int PAD = 88;
constexpr int TILE_ELE = 128 * PAD;
constexpr int ATTN_SMEM = 5 * TILE_ELE * 2;   // 112640 B

__global__ __launch_bounds__(256, 2) void attn_kernel(const float* __restrict__ x1,
                                                      const float* __restrict__ x2,
                                                      float* __restrict__ out) {
    extern __shared__ __half smb[];
    __half* QH = smb;

    const int br = blockIdx.z;
    const int bh = blockIdx.y;
    const int bb = bh >> 3;
    const int hh = bh & 7;
    const int qt = blockIdx.x;

    const float* __restrict__ q_g = (br ? x2 : x1)
        + (size_t)bb * NSEQ * C_DIM + (size_t)qt * 128 * C_DIM + hh * HD;
    const __half* __restrict__ KHg = g_kvh[1 - br];
    const __half* __restrict__ VHg = g_kvh[br];
    float* __restrict__ o_g = out + (size_t)br * NB * NSEQ * C_DIM
        + (size_t)bb * NSEQ * C_DIM + (size_t)qt * 128 * C_DIM + hh * HD;

    const int tid  = threadIdx.x;
    const int w    = tid >> 5;
    const int lane = tid & 31;
    const int g    = lane >> 2;
    const int tq   = lane & 3;

    const size_t kv_row0 = (size_t)bb * NSEQ;
    const int kcol = hh * HD;
    const int vcol = C_DIM + hh * HD;

    int cm[4], cd[4];
    #pragma unroll
    for (int l = 0; l < 4; l++) {
        const int c = tid + l * 256;
        cm[l] = c >> 3;
        cd[l] = (c & 7) * 8;
    }

    auto issue = [&](int mt, int p) {
        __half* KH = smb + (1 + p * 2 + 0) * TILE_ELE;
        __half* VH = smb + (1 + p * 2 + 1) * TILE_ELE;
        const size_t rbase = kv_row0 + (size_t)mt * 128;
        #pragma unroll
        for (int l = 0; l < 4; l++) {
            const size_t gidx = (rbase + cm[l]) * KVN;
            const int so = cm[l] * PAD + cd[l];
            cp16(smem_u32(&KH[so]), &KHg[gidx + kcol + cd[l]]);
            cp16(smem_u32(&VH[so]), &VHg[gidx + vcol + cd[l]]);
        }
        cp_commit();
    };

    // ---- prologue: issue tile 0; load + scale + round Q to fp16 ----
    issue(0, 0);
    #pragma unroll
    for (int l = 0; l < 8; l++) {
        const int c   = tid + l * 256;
        const int row = c >> 4;
        const int c4  = (c & 15) * 4;
        float4 q4 = *(const float4*)&q_g[(size_t)row * C_DIM + c4];
        uint2 hv = {packH(q4.x * SCALE, q4.y * SCALE), packH(q4.z * SCALE, q4.w * SCALE)};
        *(uint2*)&QH[row * PAD + c4] = hv;
    }
    __syncthreads();

    // loop-invariant Q fragments
    const int a_row_off = (lane & 7) + ((lane >> 3) & 1) * 8;
    const int a_col_off = ((lane >> 4) & 1) * 8;
    uint32_t ah[16];
    #pragma unroll
    for (int ks = 0; ks < 4; ks++) {
        const int arow = w * 16 + a_row_off;
        const int acol = ks * 16 + a_col_off;
        ldsm_x4(&ah[ks * 4], smem_u32(&QH[arow * PAD + acol]));
    }

    float oacc[8][4] = {};
    const int b_quad = lane >> 3;
    const int b_r    = lane & 7;

    for (int mt = 0; mt < 8; mt++) {
        cp_wait0();
        __syncthreads();
        if (mt + 1 < 8) issue(mt + 1, (mt + 1) & 1);

        const int p = mt & 1;
        const __half* KH = smb + (1 + p * 2 + 0) * TILE_ELE;
        const __half* VH = smb + (1 + p * 2 + 1) * TILE_ELE;

        #pragma unroll
        for (int j = 0; j < 8; j++) {
            const int bcol  = b_quad * 8;
            const int brow0 = (2 * j + 0) * 8 + b_r;
            const int brow1 = (2 * j + 1) * 8 + b_r;
            uint32_t bh0[8], bh1[8];
            ldsm_x4(&bh0[0], smem_u32(&KH[brow0 * PAD + bcol]));
            ldsm_x4(&bh0[4], smem_u32(&KH[brow0 * PAD + 32 + bcol]));
            ldsm_x4(&bh1[0], smem_u32(&KH[brow1 * PAD + bcol]));
            ldsm_x4(&bh1[4], smem_u32(&KH[brow1 * PAD + 32 + bcol]));

            // ---- stage 1: fp16-accumulated, 2 chains; outputs ARE the A-frags ----
            uint32_t s0[2] = {0u, 0u}, s1[2] = {0u, 0u};
            #pragma unroll
            for (int ks = 0; ks < 4; ks++) {
                mmaHf16(s0, &ah[ks * 4], &bh0[ks * 2]);
                mmaHf16(s1, &ah[ks * 4], &bh1[ks * 2]);
            }
            uint32_t sah[4];
            sah[0] = hmax2z(s0[0]);
            sah[1] = hmax2z(s0[1]);
            sah[2] = hmax2z(s1[0]);
            sah[3] = hmax2z(s1[1]);

            // ---- stage 2: O += S . v  (8 independent fp32 accumulators) ----
            const int vrow = j * 16 + (b_quad & 1) * 8 + b_r;
            #pragma unroll
            for (int np = 0; np < 4; np++) {
                const int col = np * 16 + (b_quad >> 1) * 8;
                uint32_t bvh[4];
                ldsm_x4t(bvh, smem_u32(&VH[vrow * PAD + col]));
                mmaH(oacc[2 * np],     sah, &bvh[0]);
                mmaH(oacc[2 * np + 1], sah, &bvh[2]);
            }
        }
        __syncthreads();
    }

    #pragma unroll
    for (int nt2 = 0; nt2 < 8; nt2++) {
        float2 v0 = {oacc[nt2][0], oacc[nt2][1]};
        float2 v1 = {oacc[nt2][2], oacc[nt2][3]};
        *(float2*)&o_g[(size_t)(w * 16 + g) * C_DIM + nt2 * 8 + 2 * tq] = v0;
        *(float2*)&o_g[(size_t)(w * 16 + g + 8) * C_DIM + nt2 * 8 + 2 * tq] = v1;
    }
}

// ---------------------------------------------------------------------------
extern "C" void kernel_launch(void* const* d_in, const int* in_sizes, int n_in,
                              void* d_out, int out_size) {
    const float* x1 = (const float*)d_in[0];
    const float* x2 = (const float*)d_in[1];
    const float* w1 = (const float*)d_in[2];
    const float* w2 = (const float*)d_in[3];
    float* out = (float*)d_out;

    (void)cudaFuncSetAttribute(attn_kernel,
                               cudaFuncAttributeMaxDynamicSharedMemorySize, ATTN_SMEM);
    (void)cudaFuncSetAttribute(kv_gemm,
                               cudaFuncAttributeMaxDynamicSharedMemorySize, KV_SMEM);

    __half* wh0;
    (void)cudaGetSymbolAddress((void**)&wh0, g_wh);

    split_w<<<(WTOT4 + 255) / 256, 256>>>(w1, w2, wh0);

    dim3 g1(KVN / 128, M_TOT / 128, 2);
    kv_gemm<<<g1, 256, KV_SMEM>>>(x1, x2);

    dim3 g2(NSEQ / 128, NB * NHEADS, 2);
    attn_kernel<<<g2, 256, ATTN_SMEM>>>(x1, x2, out);
}